// round 8
// baseline (speedup 1.0000x reference)
#include <cuda_runtime.h>
#include <cuda_bf16.h>
#include <cuda_fp16.h>
#include <stdint.h>
#include <math.h>

// ---------------------------------------------------------------- constants
#define M_BATCH   8192
#define N_NODES   1023
#define N_PAD     1024
#define K_DIM     1024
#define N_CLASSES 10
#define N_LEAVES  1024

// GEMM tiling: CTA 128x128, 4 warps of 64x64 (2M x 2N), 3-stage cp.async
#define GBM 128
#define GBN 128
#define GBK 64                        // bf16 per K-chunk = 128B row
#define NCHUNK (K_DIM / GBK)          // 16
#define STAGES 3
#define TILE_B 16384                  // one 128x64 bf16 tile, bytes
#define STAGE_B (2 * TILE_B)          // A+B per stage
#define GEMM_SMEM (STAGES * STAGE_B)  // 98304

// prep kernel block ranges (each thread: 8 floats = 2 float4)
#define PREP_X_BLOCKS 4096            // 8M floats / (256*8)
#define PREP_W_BLOCKS 512             // 1M floats / (256*8)
#define PREP_L_BLOCKS 4
#define PREP_BLOCKS (PREP_X_BLOCKS + PREP_W_BLOCKS + PREP_L_BLOCKS)

// ---------------------------------------------------------------- scratch
__device__ __nv_bfloat16 g_xb[(size_t)M_BATCH * K_DIM];   // 16 MB
__device__ __nv_bfloat16 g_wb[(size_t)N_PAD * K_DIM];     // 2 MB (row 1023 zero)
__device__ __half g_probs[(size_t)M_BATCH * N_PAD];       // 16 MB
__device__ float g_leaf_reward[N_LEAVES];

// ---------------------------------------------------------------- helpers
__device__ __forceinline__ uint32_t s2u(const void* p) {
    uint32_t a;
    asm("{ .reg .u64 t; cvta.to.shared.u64 t, %1; cvt.u32.u64 %0, t; }"
        : "=r"(a) : "l"(p));
    return a;
}
__device__ __forceinline__ uint32_t swz(uint32_t o) { return o ^ ((o >> 3) & 0x70); }

__device__ __forceinline__ uint32_t bf2x(float a, float b) {
    __nv_bfloat162 h = __floats2bfloat162_rn(a, b);
    return *reinterpret_cast<uint32_t*>(&h);
}

#define LDSM_X4(r0, r1, r2, r3, a)                                             \
    asm volatile("ldmatrix.sync.aligned.m8n8.x4.shared.b16 {%0,%1,%2,%3}, [%4];" \
        : "=r"(r0), "=r"(r1), "=r"(r2), "=r"(r3) : "r"(a))

#define MMA16816(c, a, b0, b1)                                                 \
    asm volatile("mma.sync.aligned.m16n8k16.row.col.f32.bf16.bf16.f32 "        \
        "{%0,%1,%2,%3}, {%4,%5,%6,%7}, {%8,%9}, {%0,%1,%2,%3};"                \
        : "+f"((c)[0]), "+f"((c)[1]), "+f"((c)[2]), "+f"((c)[3])               \
        : "r"((a)[0]), "r"((a)[1]), "r"((a)[2]), "r"((a)[3]),                  \
          "r"(b0), "r"(b1))

// ---------------------------------------------------------------------------
// Kernel 1: fused prep — convert x, convert+pad W, leaf_reward.
//   Packed uint2 bf16 stores; 2 independent float4 loads per thread (MLP).
// ---------------------------------------------------------------------------
__global__ __launch_bounds__(256)
void prep_kernel(const float* __restrict__ x,
                 const float* __restrict__ W,
                 const float* __restrict__ leaf_dist,
                 const float* __restrict__ class_reward) {
    int blk = blockIdx.x;
    if (blk < PREP_X_BLOCKS) {
        size_t base = ((size_t)blk * 256 + threadIdx.x) * 4;   // two halves, 4M apart
        float4 v0 = *reinterpret_cast<const float4*>(x + base);
        float4 v1 = *reinterpret_cast<const float4*>(x + base + 1024 * 4096);
        *reinterpret_cast<uint2*>(g_xb + base) =
            make_uint2(bf2x(v0.x, v0.y), bf2x(v0.z, v0.w));
        *reinterpret_cast<uint2*>(g_xb + base + 1024 * 4096) =
            make_uint2(bf2x(v1.x, v1.y), bf2x(v1.z, v1.w));
    } else if (blk < PREP_X_BLOCKS + PREP_W_BLOCKS) {
        size_t base = ((size_t)(blk - PREP_X_BLOCKS) * 256 + threadIdx.x) * 4;
#pragma unroll
        for (int h = 0; h < 2; h++) {
            size_t i = base + (size_t)h * (512 * 1024);
            int row = (int)(i >> 10);
            uint2 o;
            if (row < N_NODES) {
                float4 v = *reinterpret_cast<const float4*>(W + i);
                o = make_uint2(bf2x(v.x, v.y), bf2x(v.z, v.w));
            } else {
                o = make_uint2(0u, 0u);
            }
            *reinterpret_cast<uint2*>(g_wb + i) = o;
        }
    } else {
        int l = (blk - PREP_X_BLOCKS - PREP_W_BLOCKS) * 256 + threadIdx.x;
        if (l >= N_LEAVES) return;
        float v[N_CLASSES];
        float mx = -1e30f;
#pragma unroll
        for (int c = 0; c < N_CLASSES; c++) {
            v[c] = leaf_dist[l * N_CLASSES + c];
            mx = fmaxf(mx, v[c]);
        }
        float s = 0.f;
#pragma unroll
        for (int c = 0; c < N_CLASSES; c++) { v[c] = expf(v[c] - mx); s += v[c]; }
        float inv = 1.f / s, r = 0.f;
#pragma unroll
        for (int c = 0; c < N_CLASSES; c++) r += v[c] * inv * class_reward[c];
        g_leaf_reward[l] = r;
    }
}

// ---------------------------------------------------------------------------
// Kernel 2: bf16 warp-MMA GEMM, 4 warps (2Mx2N), warp tile 64x64.
//   Per k16 step: 8 ldsm.x4 feed 32 HMMAs (MMA:LDSM ratio 4.0 vs 2.67 before).
// ---------------------------------------------------------------------------
__global__ __launch_bounds__(128, 2)
void gemm_bf16_kernel(const float* __restrict__ bvec,
                      const float* __restrict__ beta) {
    extern __shared__ char smem[];
    const uint32_t sb = s2u(smem);
    const int tid  = threadIdx.x;
    const int wid  = tid >> 5, lane = tid & 31;
    const int wm   = wid & 1;            // 0..1 -> 64 M-rows
    const int wn   = wid >> 1;           // 0..1 -> 64 N-cols
    const int m0   = blockIdx.y * GBM;
    const int n0   = blockIdx.x * GBN;

    const int g = lane >> 3;             // ldmatrix 8-thread group
    const int r = lane & 7;

    const __nv_bfloat16* ag = g_xb + (size_t)m0 * K_DIM;
    const __nv_bfloat16* bg = g_wb + (size_t)n0 * K_DIM;

    // stage loader: 128x64 A + 128x64 B, 128 threads x 8 lines each per tile
#define LOAD_STAGE(ck) do {                                                    \
    uint32_t _st = sb + ((ck) % STAGES) * STAGE_B;                             \
    _Pragma("unroll")                                                          \
    for (int _u = 0; _u < 8; _u++) {                                           \
        int _c = tid + 128 * _u;                                               \
        int _row = _c >> 3, _seg = _c & 7;                                     \
        uint32_t _off = swz((uint32_t)(_row * 128 + _seg * 16));               \
        const void* _as = ag + (size_t)_row * K_DIM + (ck) * GBK + _seg * 8;   \
        const void* _bs = bg + (size_t)_row * K_DIM + (ck) * GBK + _seg * 8;   \
        asm volatile("cp.async.cg.shared.global [%0], [%1], 16;"               \
                     :: "r"(_st + _off), "l"(_as));                            \
        asm volatile("cp.async.cg.shared.global [%0], [%1], 16;"               \
                     :: "r"(_st + TILE_B + _off), "l"(_bs));                   \
    }                                                                          \
    asm volatile("cp.async.commit_group;" ::: "memory");                       \
} while (0)

    float acc[4][8][4];
#pragma unroll
    for (int i = 0; i < 4; i++)
#pragma unroll
        for (int j = 0; j < 8; j++)
#pragma unroll
            for (int c = 0; c < 4; c++) acc[i][j][c] = 0.f;

    // A x4 (16x16): row = wm*64 + i*16 + r + (g&1)*8 ; k add = (g>>1)*16
    // B x4 (n16xk16): row = wn*64 + j2*16 + r + (g>>1)*8 ; k add = (g&1)*16
    const int a_kadd = (g >> 1) * 16;
    const int b_kadd = (g & 1) * 16;

    LOAD_STAGE(0);
    LOAD_STAGE(1);

    for (int it = 0; it < NCHUNK; it++) {
        if (it + 1 < NCHUNK) asm volatile("cp.async.wait_group 1;" ::: "memory");
        else                 asm volatile("cp.async.wait_group 0;" ::: "memory");
        __syncthreads();

        if (it + 2 < NCHUNK) LOAD_STAGE(it + 2);

        const uint32_t stA = sb + (it % STAGES) * STAGE_B;
        const uint32_t stB = stA + TILE_B;

#pragma unroll
        for (int s = 0; s < 4; s++) {            // 4 x k16 steps per chunk
            uint32_t a[4][4];
#pragma unroll
            for (int i = 0; i < 4; i++) {
                int row = wm * 64 + i * 16 + r + (g & 1) * 8;
                uint32_t addr = stA + (uint32_t)(row * 128)
                              + (uint32_t)((s * 32 + a_kadd) ^ ((row & 7) * 16));
                LDSM_X4(a[i][0], a[i][1], a[i][2], a[i][3], addr);
            }
            uint32_t bf[8][2];
#pragma unroll
            for (int j = 0; j < 4; j++) {        // n16 groups
                int row = wn * 64 + j * 16 + r + (g >> 1) * 8;
                uint32_t addr = stB + (uint32_t)(row * 128)
                              + (uint32_t)((s * 32 + b_kadd) ^ ((row & 7) * 16));
                LDSM_X4(bf[2 * j][0], bf[2 * j][1], bf[2 * j + 1][0], bf[2 * j + 1][1], addr);
            }
#pragma unroll
            for (int i = 0; i < 4; i++)
#pragma unroll
                for (int j = 0; j < 8; j++)
                    MMA16816(acc[i][j], a[i], bf[j][0], bf[j][1]);
        }
    }
    __syncthreads();

    // ---- stage bias/beta (reuse stage-0 smem), then fused sigmoid + fp16 store
    float* bs = reinterpret_cast<float*>(smem);
    float* es = bs + 128;
    if (tid < 128) {
        int n = n0 + tid;
        bs[tid] = (n < N_NODES) ? bvec[n] : 0.f;
        es[tid] = (n < N_NODES) ? beta[n] : 0.f;
    }
    __syncthreads();

    const int qr = lane >> 2;          // 0..7
    const int qc = lane & 3;           // 0..3
#pragma unroll
    for (int i = 0; i < 4; i++) {
        int mA = m0 + wm * 64 + i * 16 + qr;
#pragma unroll
        for (int j = 0; j < 8; j++) {
            int nl = wn * 64 + j * 8 + 2 * qc;   // local col (pair)
            float b0 = bs[nl],     e0 = es[nl];
            float b1 = bs[nl + 1], e1 = es[nl + 1];
            float z0 = e0 * (acc[i][j][0] + b0);
            float z1 = e1 * (acc[i][j][1] + b1);
            float z2 = e0 * (acc[i][j][2] + b0);
            float z3 = e1 * (acc[i][j][3] + b1);
            __half2 v0 = __floats2half2_rn(1.f / (1.f + __expf(-z0)),
                                           1.f / (1.f + __expf(-z1)));
            __half2 v1 = __floats2half2_rn(1.f / (1.f + __expf(-z2)),
                                           1.f / (1.f + __expf(-z3)));
            *reinterpret_cast<__half2*>(&g_probs[(size_t)mA * N_PAD + n0 + nl]) = v0;
            *reinterpret_cast<__half2*>(&g_probs[(size_t)(mA + 8) * N_PAD + n0 + nl]) = v1;
        }
    }
}

// ---------------------------------------------------------------------------
// Kernel 3: warp-per-row tree fold (unchanged — measured fast)
// ---------------------------------------------------------------------------
#define FOLD_ROWS 8
__device__ __forceinline__ int lpad(int i) { return i + (i >> 5); }

__global__ __launch_bounds__(256)
void fold_kernel(float* __restrict__ out) {
    __shared__ float Lr[N_LEAVES + N_LEAVES / 32];

    const int tid  = threadIdx.x;
    const int wrp  = tid >> 5;
    const int lane = tid & 31;
    const int row  = blockIdx.x * FOLD_ROWS + wrp;

    for (int i = tid; i < N_LEAVES; i += 256) Lr[lpad(i)] = g_leaf_reward[i];
    __syncthreads();

    const __half* p = g_probs + (size_t)row * N_PAD;

    float v[16];
    {
        const int base9 = 511 + 16 * lane;
#pragma unroll
        for (int i = 0; i < 16; i++) {
            float pp = __half2float(__ldg(p + base9 + i));
            float l0 = Lr[lpad(32 * lane + 2 * i)];
            float l1 = Lr[lpad(32 * lane + 2 * i + 1)];
            v[i] = pp * l0 + (1.f - pp) * l1;
        }
        const int base8 = 255 + 8 * lane;
#pragma unroll
        for (int i = 0; i < 8; i++) {
            float pp = __half2float(__ldg(p + base8 + i));
            v[i] = pp * v[2 * i] + (1.f - pp) * v[2 * i + 1];
        }
        const int base7 = 127 + 4 * lane;
#pragma unroll
        for (int i = 0; i < 4; i++) {
            float pp = __half2float(__ldg(p + base7 + i));
            v[i] = pp * v[2 * i] + (1.f - pp) * v[2 * i + 1];
        }
        const int base6 = 63 + 2 * lane;
#pragma unroll
        for (int i = 0; i < 2; i++) {
            float pp = __half2float(__ldg(p + base6 + i));
            v[i] = pp * v[2 * i] + (1.f - pp) * v[2 * i + 1];
        }
        float pp = __half2float(__ldg(p + 31 + lane));
        v[0] = pp * v[0] + (1.f - pp) * v[1];
    }

    float vv = v[0];
#pragma unroll
    for (int lvl = 4; lvl >= 0; lvl--) {
        int cnt = 1 << lvl;
        float vl = __shfl_sync(0xFFFFFFFFu, vv, 2 * lane);
        float vr = __shfl_sync(0xFFFFFFFFu, vv, 2 * lane + 1);
        float pp = (lane < cnt) ? __half2float(__ldg(p + cnt - 1 + lane)) : 0.f;
        vv = pp * vl + (1.f - pp) * vr;
    }
    if (lane == 0) out[row] = vv;
}

// ---------------------------------------------------------------------------
// kernel_launch: x, W, b, beta, leaf_dist, class_reward -> loss[8192]
// ---------------------------------------------------------------------------
extern "C" void kernel_launch(void* const* d_in, const int* in_sizes, int n_in,
                              void* d_out, int out_size) {
    const float* x            = (const float*)d_in[0];
    const float* W            = (const float*)d_in[1];
    const float* b            = (const float*)d_in[2];
    const float* beta         = (const float*)d_in[3];
    const float* leaf_dist    = (const float*)d_in[4];
    const float* class_reward = (const float*)d_in[5];
    float* out = (float*)d_out;

    cudaFuncSetAttribute(gemm_bf16_kernel,
                         cudaFuncAttributeMaxDynamicSharedMemorySize, GEMM_SMEM);

    prep_kernel<<<PREP_BLOCKS, 256>>>(x, W, leaf_dist, class_reward);

    dim3 grid(N_PAD / GBN, M_BATCH / GBM);   // 8 x 64
    gemm_bf16_kernel<<<grid, 128, GEMM_SMEM>>>(b, beta);

    fold_kernel<<<M_BATCH / FOLD_ROWS, 256>>>(out);
}

// round 9
// speedup vs baseline: 1.0756x; 1.0756x over previous
#include <cuda_runtime.h>
#include <cuda_bf16.h>
#include <cuda_fp16.h>
#include <stdint.h>
#include <math.h>

// ---------------------------------------------------------------- constants
#define M_BATCH   8192
#define N_NODES   1023
#define N_PAD     1024
#define K_DIM     1024
#define N_CLASSES 10
#define N_LEAVES  1024

// GEMM tiling: CTA 128x128, 8 warps 4(M)x2(N) of 32x64, 3-stage cp.async
#define GBM 128
#define GBN 128
#define GBK 64                        // bf16 per K-chunk = 128B row
#define NCHUNK (K_DIM / GBK)          // 16
#define STAGES 3
#define TILE_B 16384                  // one 128x64 bf16 tile, bytes
#define STAGE_B (2 * TILE_B)          // A+B per stage
#define GEMM_SMEM (STAGES * STAGE_B)  // 98304

// prep kernel block ranges (each thread: 8 floats = 2 float4)
#define PREP_X_BLOCKS 4096
#define PREP_W_BLOCKS 512
#define PREP_L_BLOCKS 4
#define PREP_BLOCKS (PREP_X_BLOCKS + PREP_W_BLOCKS + PREP_L_BLOCKS)

// ---------------------------------------------------------------- scratch
__device__ __nv_bfloat16 g_xb[(size_t)M_BATCH * K_DIM];   // 16 MB
__device__ __nv_bfloat16 g_wb[(size_t)N_PAD * K_DIM];     // 2 MB (row 1023 zero)
__device__ __half g_probs[(size_t)M_BATCH * N_PAD];       // 16 MB
__device__ float g_leaf_reward[N_LEAVES];

// ---------------------------------------------------------------- helpers
__device__ __forceinline__ uint32_t s2u(const void* p) {
    uint32_t a;
    asm("{ .reg .u64 t; cvta.to.shared.u64 t, %1; cvt.u32.u64 %0, t; }"
        : "=r"(a) : "l"(p));
    return a;
}
__device__ __forceinline__ uint32_t swz(uint32_t o) { return o ^ ((o >> 3) & 0x70); }

__device__ __forceinline__ uint32_t bf2x(float a, float b) {
    __nv_bfloat162 h = __floats2bfloat162_rn(a, b);
    return *reinterpret_cast<uint32_t*>(&h);
}

#define LDSM_X4(r0, r1, r2, r3, a)                                             \
    asm volatile("ldmatrix.sync.aligned.m8n8.x4.shared.b16 {%0,%1,%2,%3}, [%4];" \
        : "=r"(r0), "=r"(r1), "=r"(r2), "=r"(r3) : "r"(a))

#define MMA16816(c, a, b0, b1)                                                 \
    asm volatile("mma.sync.aligned.m16n8k16.row.col.f32.bf16.bf16.f32 "        \
        "{%0,%1,%2,%3}, {%4,%5,%6,%7}, {%8,%9}, {%0,%1,%2,%3};"                \
        : "+f"((c)[0]), "+f"((c)[1]), "+f"((c)[2]), "+f"((c)[3])               \
        : "r"((a)[0]), "r"((a)[1]), "r"((a)[2]), "r"((a)[3]),                  \
          "r"(b0), "r"(b1))

// ---------------------------------------------------------------------------
// Kernel 1: fused prep — convert x, convert+pad W, leaf_reward.
//   Packed uint2 bf16 stores; 2 independent float4 loads per thread (MLP).
// ---------------------------------------------------------------------------
__global__ __launch_bounds__(256)
void prep_kernel(const float* __restrict__ x,
                 const float* __restrict__ W,
                 const float* __restrict__ leaf_dist,
                 const float* __restrict__ class_reward) {
    int blk = blockIdx.x;
    if (blk < PREP_X_BLOCKS) {
        size_t base = ((size_t)blk * 256 + threadIdx.x) * 4;
        float4 v0 = *reinterpret_cast<const float4*>(x + base);
        float4 v1 = *reinterpret_cast<const float4*>(x + base + 1024 * 4096);
        *reinterpret_cast<uint2*>(g_xb + base) =
            make_uint2(bf2x(v0.x, v0.y), bf2x(v0.z, v0.w));
        *reinterpret_cast<uint2*>(g_xb + base + 1024 * 4096) =
            make_uint2(bf2x(v1.x, v1.y), bf2x(v1.z, v1.w));
    } else if (blk < PREP_X_BLOCKS + PREP_W_BLOCKS) {
        size_t base = ((size_t)(blk - PREP_X_BLOCKS) * 256 + threadIdx.x) * 4;
#pragma unroll
        for (int h = 0; h < 2; h++) {
            size_t i = base + (size_t)h * (512 * 1024);
            int row = (int)(i >> 10);
            uint2 o;
            if (row < N_NODES) {
                float4 v = *reinterpret_cast<const float4*>(W + i);
                o = make_uint2(bf2x(v.x, v.y), bf2x(v.z, v.w));
            } else {
                o = make_uint2(0u, 0u);
            }
            *reinterpret_cast<uint2*>(g_wb + i) = o;
        }
    } else {
        int l = (blk - PREP_X_BLOCKS - PREP_W_BLOCKS) * 256 + threadIdx.x;
        if (l >= N_LEAVES) return;
        float v[N_CLASSES];
        float mx = -1e30f;
#pragma unroll
        for (int c = 0; c < N_CLASSES; c++) {
            v[c] = leaf_dist[l * N_CLASSES + c];
            mx = fmaxf(mx, v[c]);
        }
        float s = 0.f;
#pragma unroll
        for (int c = 0; c < N_CLASSES; c++) { v[c] = expf(v[c] - mx); s += v[c]; }
        float inv = 1.f / s, r = 0.f;
#pragma unroll
        for (int c = 0; c < N_CLASSES; c++) r += v[c] * inv * class_reward[c];
        g_leaf_reward[l] = r;
    }
}

// ---------------------------------------------------------------------------
// Kernel 2: bf16 warp-MMA GEMM, 8 warps 4(M)x2(N), warp tile 32x64.
//   K-step accumulation is commutative: warp w walks k-steps in order
//   (s + w) & 3 so warps are phase-offset — LDSM bursts of some warps
//   overlap MMA bursts of others instead of all hitting the smem port
//   simultaneously after each __syncthreads.
// ---------------------------------------------------------------------------
__global__ __launch_bounds__(256)
void gemm_bf16_kernel(const float* __restrict__ bvec,
                      const float* __restrict__ beta) {
    extern __shared__ char smem[];
    const uint32_t sb = s2u(smem);
    const int tid  = threadIdx.x;
    const int wid  = tid >> 5, lane = tid & 31;
    const int wm   = wid & 3;            // 0..3  -> 32 M-rows each
    const int wn   = wid >> 2;           // 0..1  -> 64 N-cols each
    const int m0   = blockIdx.y * GBM;
    const int n0   = blockIdx.x * GBN;

    const int g = lane >> 3;             // ldmatrix 8-thread group
    const int r = lane & 7;

    const __nv_bfloat16* ag = g_xb + (size_t)m0 * K_DIM;
    const __nv_bfloat16* bg = g_wb + (size_t)n0 * K_DIM;

#define LOAD_STAGE(ck) do {                                                    \
    uint32_t _st = sb + ((ck) % STAGES) * STAGE_B;                             \
    _Pragma("unroll")                                                          \
    for (int _u = 0; _u < 4; _u++) {                                           \
        int _c = tid + 256 * _u;                                               \
        int _row = _c >> 3, _seg = _c & 7;                                     \
        uint32_t _off = swz((uint32_t)(_row * 128 + _seg * 16));               \
        const void* _as = ag + (size_t)_row * K_DIM + (ck) * GBK + _seg * 8;   \
        const void* _bs = bg + (size_t)_row * K_DIM + (ck) * GBK + _seg * 8;   \
        asm volatile("cp.async.cg.shared.global [%0], [%1], 16;"               \
                     :: "r"(_st + _off), "l"(_as));                            \
        asm volatile("cp.async.cg.shared.global [%0], [%1], 16;"               \
                     :: "r"(_st + TILE_B + _off), "l"(_bs));                   \
    }                                                                          \
    asm volatile("cp.async.commit_group;" ::: "memory");                       \
} while (0)

    float acc[2][8][4];
#pragma unroll
    for (int i = 0; i < 2; i++)
#pragma unroll
        for (int j = 0; j < 8; j++)
#pragma unroll
            for (int c = 0; c < 4; c++) acc[i][j][c] = 0.f;

    const int a_row[2] = { wm * 32 + 0 * 16 + r + (g & 1) * 8,
                           wm * 32 + 1 * 16 + r + (g & 1) * 8 };
    const int a_kadd   = (g >> 1) * 16;
    const int b_kadd   = (g & 1) * 16;
    const int srot     = wid & 3;        // per-warp k-step phase offset

    LOAD_STAGE(0);
    LOAD_STAGE(1);

    for (int it = 0; it < NCHUNK; it++) {
        if (it + 1 < NCHUNK) asm volatile("cp.async.wait_group 1;" ::: "memory");
        else                 asm volatile("cp.async.wait_group 0;" ::: "memory");
        __syncthreads();

        if (it + 2 < NCHUNK) LOAD_STAGE(it + 2);

        const uint32_t stA = sb + (it % STAGES) * STAGE_B;
        const uint32_t stB = stA + TILE_B;

#pragma unroll
        for (int s0 = 0; s0 < 4; s0++) {         // rotated k16 step order
            const int s = (s0 + srot) & 3;
            uint32_t a[2][4];
#pragma unroll
            for (int i = 0; i < 2; i++) {
                int row = a_row[i];
                uint32_t addr = stA + (uint32_t)(row * 128)
                              + (uint32_t)((s * 32 + a_kadd) ^ ((row & 7) * 16));
                LDSM_X4(a[i][0], a[i][1], a[i][2], a[i][3], addr);
            }
            uint32_t bf[8][2];
#pragma unroll
            for (int j = 0; j < 4; j++) {        // n16 groups
                int row = wn * 64 + j * 16 + r + (g >> 1) * 8;
                uint32_t addr = stB + (uint32_t)(row * 128)
                              + (uint32_t)((s * 32 + b_kadd) ^ ((row & 7) * 16));
                LDSM_X4(bf[2 * j][0], bf[2 * j][1], bf[2 * j + 1][0], bf[2 * j + 1][1], addr);
            }
#pragma unroll
            for (int i = 0; i < 2; i++)
#pragma unroll
                for (int j = 0; j < 8; j++)
                    MMA16816(acc[i][j], a[i], bf[j][0], bf[j][1]);
        }
    }
    __syncthreads();

    // ---- stage bias/beta (reuse stage-0 smem), then fused sigmoid + fp16 store
    float* bs = reinterpret_cast<float*>(smem);
    float* es = bs + 128;
    if (tid < 128) {
        int n = n0 + tid;
        bs[tid] = (n < N_NODES) ? bvec[n] : 0.f;
        es[tid] = (n < N_NODES) ? beta[n] : 0.f;
    }
    __syncthreads();

    const int qr = lane >> 2;          // 0..7
    const int qc = lane & 3;           // 0..3
#pragma unroll
    for (int i = 0; i < 2; i++) {
        int mA = m0 + wm * 32 + i * 16 + qr;
#pragma unroll
        for (int j = 0; j < 8; j++) {
            int nl = wn * 64 + j * 8 + 2 * qc;
            float b0 = bs[nl],     e0 = es[nl];
            float b1 = bs[nl + 1], e1 = es[nl + 1];
            float z0 = e0 * (acc[i][j][0] + b0);
            float z1 = e1 * (acc[i][j][1] + b1);
            float z2 = e0 * (acc[i][j][2] + b0);
            float z3 = e1 * (acc[i][j][3] + b1);
            __half2 v0 = __floats2half2_rn(1.f / (1.f + __expf(-z0)),
                                           1.f / (1.f + __expf(-z1)));
            __half2 v1 = __floats2half2_rn(1.f / (1.f + __expf(-z2)),
                                           1.f / (1.f + __expf(-z3)));
            *reinterpret_cast<__half2*>(&g_probs[(size_t)mA * N_PAD + n0 + nl]) = v0;
            *reinterpret_cast<__half2*>(&g_probs[(size_t)(mA + 8) * N_PAD + n0 + nl]) = v1;
        }
    }
}

// ---------------------------------------------------------------------------
// Kernel 3: warp-per-row tree fold (unchanged — measured fast)
// ---------------------------------------------------------------------------
#define FOLD_ROWS 8
__device__ __forceinline__ int lpad(int i) { return i + (i >> 5); }

__global__ __launch_bounds__(256)
void fold_kernel(float* __restrict__ out) {
    __shared__ float Lr[N_LEAVES + N_LEAVES / 32];

    const int tid  = threadIdx.x;
    const int wrp  = tid >> 5;
    const int lane = tid & 31;
    const int row  = blockIdx.x * FOLD_ROWS + wrp;

    for (int i = tid; i < N_LEAVES; i += 256) Lr[lpad(i)] = g_leaf_reward[i];
    __syncthreads();

    const __half* p = g_probs + (size_t)row * N_PAD;

    float v[16];
    {
        const int base9 = 511 + 16 * lane;
#pragma unroll
        for (int i = 0; i < 16; i++) {
            float pp = __half2float(__ldg(p + base9 + i));
            float l0 = Lr[lpad(32 * lane + 2 * i)];
            float l1 = Lr[lpad(32 * lane + 2 * i + 1)];
            v[i] = pp * l0 + (1.f - pp) * l1;
        }
        const int base8 = 255 + 8 * lane;
#pragma unroll
        for (int i = 0; i < 8; i++) {
            float pp = __half2float(__ldg(p + base8 + i));
            v[i] = pp * v[2 * i] + (1.f - pp) * v[2 * i + 1];
        }
        const int base7 = 127 + 4 * lane;
#pragma unroll
        for (int i = 0; i < 4; i++) {
            float pp = __half2float(__ldg(p + base7 + i));
            v[i] = pp * v[2 * i] + (1.f - pp) * v[2 * i + 1];
        }
        const int base6 = 63 + 2 * lane;
#pragma unroll
        for (int i = 0; i < 2; i++) {
            float pp = __half2float(__ldg(p + base6 + i));
            v[i] = pp * v[2 * i] + (1.f - pp) * v[2 * i + 1];
        }
        float pp = __half2float(__ldg(p + 31 + lane));
        v[0] = pp * v[0] + (1.f - pp) * v[1];
    }

    float vv = v[0];
#pragma unroll
    for (int lvl = 4; lvl >= 0; lvl--) {
        int cnt = 1 << lvl;
        float vl = __shfl_sync(0xFFFFFFFFu, vv, 2 * lane);
        float vr = __shfl_sync(0xFFFFFFFFu, vv, 2 * lane + 1);
        float pp = (lane < cnt) ? __half2float(__ldg(p + cnt - 1 + lane)) : 0.f;
        vv = pp * vl + (1.f - pp) * vr;
    }
    if (lane == 0) out[row] = vv;
}

// ---------------------------------------------------------------------------
// kernel_launch: x, W, b, beta, leaf_dist, class_reward -> loss[8192]
// ---------------------------------------------------------------------------
extern "C" void kernel_launch(void* const* d_in, const int* in_sizes, int n_in,
                              void* d_out, int out_size) {
    const float* x            = (const float*)d_in[0];
    const float* W            = (const float*)d_in[1];
    const float* b            = (const float*)d_in[2];
    const float* beta         = (const float*)d_in[3];
    const float* leaf_dist    = (const float*)d_in[4];
    const float* class_reward = (const float*)d_in[5];
    float* out = (float*)d_out;

    cudaFuncSetAttribute(gemm_bf16_kernel,
                         cudaFuncAttributeMaxDynamicSharedMemorySize, GEMM_SMEM);

    prep_kernel<<<PREP_BLOCKS, 256>>>(x, W, leaf_dist, class_reward);

    dim3 grid(N_PAD / GBN, M_BATCH / GBM);   // 8 x 64
    gemm_bf16_kernel<<<grid, 256, GEMM_SMEM>>>(b, beta);

    fold_kernel<<<M_BATCH / FOLD_ROWS, 256>>>(out);
}